// round 5
// baseline (speedup 1.0000x reference)
#include <cuda_runtime.h>
#include <cuda_bf16.h>
#include <math.h>

// Problem constants
#define BB 2
#define TT 2048
#define DM 1024
#define NH 16
#define HD 64
#define MROWS (BB*TT)     // 4096

// ---------------- scratch (device globals; no allocation allowed) ----------------
__device__ __align__(16) __nv_bfloat16 g_xh[MROWS*DM], g_xl[MROWS*DM];
__device__ __align__(16) __nv_bfloat16 g_Wqh[DM*DM], g_Wql[DM*DM];
__device__ __align__(16) __nv_bfloat16 g_Wkh[DM*DM], g_Wkl[DM*DM];
__device__ __align__(16) __nv_bfloat16 g_Wvh[DM*DM], g_Wvl[DM*DM];
__device__ __align__(16) __nv_bfloat16 g_Woh[DM*DM], g_Wol[DM*DM];
__device__ __align__(16) __nv_bfloat16 g_Qh[MROWS*DM], g_Ql[MROWS*DM];
__device__ __align__(16) __nv_bfloat16 g_Kh[MROWS*DM], g_Kl[MROWS*DM];
__device__ __align__(16) __nv_bfloat16 g_Vh[MROWS*DM], g_Vl[MROWS*DM];
__device__ __align__(16) __nv_bfloat16 g_Oh[MROWS*DM], g_Ol[MROWS*DM];

// ---------------- helpers ----------------
__device__ __forceinline__ void split_bf2(float x, float y, unsigned &h, unsigned &l){
    __nv_bfloat162 hh = __floats2bfloat162_rn(x, y);
    float2 hf = __bfloat1622float2(hh);
    __nv_bfloat162 ll = __floats2bfloat162_rn(x - hf.x, y - hf.y);
    h = *(unsigned*)&hh;
    l = *(unsigned*)&ll;
}
__device__ __forceinline__ unsigned smaddr(const void* p){
    return (unsigned)__cvta_generic_to_shared(p);
}
__device__ __forceinline__ void cpa16(unsigned sdst, const void* gsrc){
    asm volatile("cp.async.cg.shared.global [%0], [%1], 16;" :: "r"(sdst), "l"(gsrc));
}
__device__ __forceinline__ void cpa_commit(){ asm volatile("cp.async.commit_group;"); }
__device__ __forceinline__ void ldsm_x4(unsigned &r0, unsigned &r1, unsigned &r2, unsigned &r3, unsigned a){
    asm volatile("ldmatrix.sync.aligned.m8n8.x4.shared.b16 {%0,%1,%2,%3}, [%4];"
        : "=r"(r0),"=r"(r1),"=r"(r2),"=r"(r3) : "r"(a));
}
__device__ __forceinline__ void ldsm_x4t(unsigned &r0, unsigned &r1, unsigned &r2, unsigned &r3, unsigned a){
    asm volatile("ldmatrix.sync.aligned.m8n8.x4.trans.shared.b16 {%0,%1,%2,%3}, [%4];"
        : "=r"(r0),"=r"(r1),"=r"(r2),"=r"(r3) : "r"(a));
}
__device__ __forceinline__ void mma16816(float c[4], const unsigned a[4], unsigned b0, unsigned b1){
    asm volatile(
      "mma.sync.aligned.m16n8k16.row.col.f32.bf16.bf16.f32 "
      "{%0,%1,%2,%3}, {%4,%5,%6,%7}, {%8,%9}, {%0,%1,%2,%3};"
      : "+f"(c[0]), "+f"(c[1]), "+f"(c[2]), "+f"(c[3])
      : "r"(a[0]), "r"(a[1]), "r"(a[2]), "r"(a[3]), "r"(b0), "r"(b1));
}

// ======================= presplit: fp32 -> bf16 hi/lo =======================
__global__ void __launch_bounds__(256) presplit_kernel(
    const float* __restrict__ src, __nv_bfloat16* __restrict__ dh,
    __nv_bfloat16* __restrict__ dl, int n4)
{
    int idx = blockIdx.x*256 + threadIdx.x;
    int stride = gridDim.x*256;
    for (; idx < n4; idx += stride){
        float4 v = ((const float4*)src)[idx];
        unsigned h0,l0,h1,l1;
        split_bf2(v.x, v.y, h0, l0);
        split_bf2(v.z, v.w, h1, l1);
        ((uint2*)dh)[idx] = make_uint2(h0,h1);
        ((uint2*)dl)[idx] = make_uint2(l0,l1);
    }
}

// ======================= pipelined bf16x3 GEMM =======================
// C[M,N] = (Ah+Al)@(Bh+Bl) (3-term) + bias. 128x128 tile, BK=32, 256 thr,
// cp.async 2-stage double buffer. out_split: 1 -> write bf16 hi/lo, 0 -> fp32.
#define GAP 40         // A smem pitch (bf16): 80B rows
#define GBP 136        // B smem pitch (bf16): 272B rows
#define SZ_A (128*GAP*2)           // 10240 B per A tile
#define SZ_B (32*GBP*2)            // 8704 B per B tile
#define OFF_AH 0
#define OFF_AL (SZ_A)
#define OFF_BH (2*SZ_A)            // 20480
#define OFF_BL (2*SZ_A + SZ_B)     // 29184
#define G_STAGE (2*SZ_A + 2*SZ_B)  // 37888
#define G_SMEM_BYTES (2*G_STAGE)   // 75776

__global__ void __launch_bounds__(256,2) gemm_bf3_kernel(
    const __nv_bfloat16* __restrict__ Agh, const __nv_bfloat16* __restrict__ Agl,
    const __nv_bfloat16* __restrict__ B0h, const __nv_bfloat16* __restrict__ B0l,
    const __nv_bfloat16* __restrict__ B1h, const __nv_bfloat16* __restrict__ B1l,
    const __nv_bfloat16* __restrict__ B2h, const __nv_bfloat16* __restrict__ B2l,
    const float* __restrict__ bb0, const float* __restrict__ bb1, const float* __restrict__ bb2,
    __nv_bfloat16* __restrict__ C0h, __nv_bfloat16* __restrict__ C0l,
    __nv_bfloat16* __restrict__ C1h, __nv_bfloat16* __restrict__ C1l,
    __nv_bfloat16* __restrict__ C2h, __nv_bfloat16* __restrict__ C2l,
    float* __restrict__ Cf, int out_split)
{
    extern __shared__ char gsm[];
    const unsigned sbase = smaddr(gsm);

    const int z = blockIdx.z;
    const __nv_bfloat16* Bh = (z==0) ? B0h : (z==1) ? B1h : B2h;
    const __nv_bfloat16* Bl = (z==0) ? B0l : (z==1) ? B1l : B2l;
    const float* bias       = (z==0) ? bb0 : (z==1) ? bb1 : bb2;
    __nv_bfloat16* Ch       = (z==0) ? C0h : (z==1) ? C1h : C2h;
    __nv_bfloat16* Cl       = (z==0) ? C0l : (z==1) ? C1l : C2l;

    const int tid  = threadIdx.x;
    const int warp = tid >> 5, lane = tid & 31;
    const int wm = warp >> 1;        // 0..3
    const int wn = warp & 1;         // 0..1
    const int bm = blockIdx.y * 128;
    const int bn = blockIdx.x * 128;

    float acc[2][8][4];
#pragma unroll
    for (int mt=0; mt<2; mt++)
#pragma unroll
      for (int nt=0; nt<8; nt++)
#pragma unroll
        for (int cc=0; cc<4; cc++) acc[mt][nt][cc] = 0.f;

    // cp.async mapping
    const int a_row = tid >> 2;          // 0..63 (+64 second)
    const int a_c8  = (tid & 3) << 3;    // bf16 col {0,8,16,24}
    const int b_row = tid >> 4;          // 0..15 (+16 second)
    const int b_c8  = (tid & 15) << 3;   // bf16 col 0..120

    // ldmatrix per-lane offsets
    const int am_r = lane & 15;
    const int am_c = (lane >> 4) << 3;
    const int bm_k = (((lane >> 3) & 1) << 3) + (lane & 7);
    const int bm_n = ((lane >> 4) & 1) << 3;

    const int la3 = lane & 3, lq = lane >> 2;

    // stage load issue
    auto issue = [&](int k0, int st){
        unsigned sb = sbase + st*G_STAGE;
#pragma unroll
        for (int p=0; p<2; p++){
            int r = a_row + p*64;
            const __nv_bfloat16* ga = Agh + (size_t)(bm + r)*DM + k0 + a_c8;
            cpa16(sb + OFF_AH + r*(GAP*2) + a_c8*2, ga);
            const __nv_bfloat16* gal = Agl + (size_t)(bm + r)*DM + k0 + a_c8;
            cpa16(sb + OFF_AL + r*(GAP*2) + a_c8*2, gal);
        }
#pragma unroll
        for (int p=0; p<2; p++){
            int r = b_row + p*16;
            const __nv_bfloat16* gb = Bh + (size_t)(k0 + r)*DM + bn + b_c8;
            cpa16(sb + OFF_BH + r*(GBP*2) + b_c8*2, gb);
            const __nv_bfloat16* gbl = Bl + (size_t)(k0 + r)*DM + bn + b_c8;
            cpa16(sb + OFF_BL + r*(GBP*2) + b_c8*2, gbl);
        }
    };

    issue(0, 0);
    cpa_commit();

    const int NK = DM/32;   // 32
    for (int it=0; it<NK; it++){
        if (it+1 < NK){
            issue((it+1)*32, (it+1)&1);
            cpa_commit();
            asm volatile("cp.async.wait_group 1;");
        } else {
            asm volatile("cp.async.wait_group 0;");
        }
        __syncthreads();

        unsigned sb = sbase + (it&1)*G_STAGE;
        unsigned uAh = sb + OFF_AH, uAl = sb + OFF_AL;
        unsigned uBh = sb + OFF_BH, uBl = sb + OFF_BL;

#pragma unroll
        for (int ks = 0; ks < 32; ks += 16){
            unsigned ahi[2][4], alo[2][4];
#pragma unroll
            for (int mt=0; mt<2; mt++){
                unsigned off = (unsigned)(((wm*32 + mt*16 + am_r)*GAP + ks + am_c)*2);
                ldsm_x4(ahi[mt][0],ahi[mt][1],ahi[mt][2],ahi[mt][3], uAh + off);
                ldsm_x4(alo[mt][0],alo[mt][1],alo[mt][2],alo[mt][3], uAl + off);
            }
#pragma unroll
            for (int np=0; np<4; np++){
                unsigned bh0,bh1,bh2,bh3, bl0,bl1,bl2,bl3;
                unsigned off = (unsigned)(((ks + bm_k)*GBP + wn*64 + np*16 + bm_n)*2);
                ldsm_x4t(bh0,bh1,bh2,bh3, uBh + off);
                ldsm_x4t(bl0,bl1,bl2,bl3, uBl + off);
#pragma unroll
                for (int mt=0; mt<2; mt++){
                    mma16816(acc[mt][2*np],   ahi[mt], bh0, bh1);
                    mma16816(acc[mt][2*np],   ahi[mt], bl0, bl1);
                    mma16816(acc[mt][2*np],   alo[mt], bh0, bh1);
                    mma16816(acc[mt][2*np+1], ahi[mt], bh2, bh3);
                    mma16816(acc[mt][2*np+1], ahi[mt], bl2, bl3);
                    mma16816(acc[mt][2*np+1], alo[mt], bh2, bh3);
                }
            }
        }
        __syncthreads();
    }

    // epilogue
#pragma unroll
    for (int mt=0; mt<2; mt++){
#pragma unroll
        for (int nt=0; nt<8; nt++){
            int col = bn + wn*64 + nt*8 + (la3<<1);
            float b0 = bias[col], b1 = bias[col+1];
            int r0 = bm + wm*32 + mt*16 + lq;
            float v00 = acc[mt][nt][0] + b0, v01 = acc[mt][nt][1] + b1;
            float v10 = acc[mt][nt][2] + b0, v11 = acc[mt][nt][3] + b1;
            if (out_split){
                unsigned h,l;
                split_bf2(v00, v01, h, l);
                *(unsigned*)&Ch[(size_t)r0*DM + col] = h;
                *(unsigned*)&Cl[(size_t)r0*DM + col] = l;
                split_bf2(v10, v11, h, l);
                *(unsigned*)&Ch[(size_t)(r0+8)*DM + col] = h;
                *(unsigned*)&Cl[(size_t)(r0+8)*DM + col] = l;
            } else {
                *(float2*)&Cf[(size_t)r0*DM + col]     = make_float2(v00, v01);
                *(float2*)&Cf[(size_t)(r0+8)*DM + col] = make_float2(v10, v11);
            }
        }
    }
}

// ======================= Fused banded attention (bf16x3, pre-split inputs) =======================
#define AQP 72    // Q pitch (bf16)
#define AKP 72    // K/V pitch (bf16)
#define APP 264   // P pitch (bf16)

#define O_PH 0
#define O_PL (O_PH + 64*APP*2)            // 33792
#define O_QH 0                            // aliases P (Q dies before P is written)
#define O_QL (O_QH + 64*AQP*2)            // 9216
#define O_KH (O_PL + 64*APP*2)            // 67584
#define O_KL (O_KH + 256*AKP*2)           // 104448
#define O_VH O_KH
#define O_VL O_KL
#define O_RM (O_KL + 256*AKP*2)           // 141312
#define O_RS (O_RM + 512)                 // 141824
#define A_SMEM_BYTES (O_RS + 512)         // 142336

__global__ void __launch_bounds__(256) attn_kernel(float* __restrict__ attn_out, int has_attn)
{
    extern __shared__ char smb[];
    unsigned short* Qh = (unsigned short*)(smb + O_QH);
    unsigned short* Ql = (unsigned short*)(smb + O_QL);
    unsigned short* Kh = (unsigned short*)(smb + O_KH);
    unsigned short* Kl = (unsigned short*)(smb + O_KL);
    unsigned short* Vh = (unsigned short*)(smb + O_VH);
    unsigned short* Vl = (unsigned short*)(smb + O_VL);
    unsigned short* Ph = (unsigned short*)(smb + O_PH);
    unsigned short* Pl = (unsigned short*)(smb + O_PL);
    float* Rm = (float*)(smb + O_RM);
    float* Rs = (float*)(smb + O_RS);

    const int tid = threadIdx.x, warp = tid>>5, lane = tid&31;
    const int wm = warp >> 1;
    const int wn = warp & 1;
    const int la3 = lane & 3;
    const int lq  = lane >> 2;
    const int bh = blockIdx.y;
    const int b = bh >> 4, h = bh & 15;
    const int qbase = blockIdx.x * 64;
    const int qblk  = qbase >> 7;
    const int kstart = (qblk==0) ? 0 : (qblk-1)*128;

    const int am_r = lane & 15;
    const int am_c = (lane >> 4) << 3;
    const int t_k = (((lane >> 3) & 1) << 3) + (lane & 7);
    const int t_n = ((lane >> 4) & 1) << 3;
    const int n_r = ((((lane >> 3) & 2) << 2)) + (lane & 7);
    const int n_k = (((lane >> 3) & 1) << 3);

    const unsigned uQh = smaddr(Qh), uQl = smaddr(Ql);
    const unsigned uKh = smaddr(Kh), uKl = smaddr(Kl);
    const unsigned uVh = smaddr(Vh), uVl = smaddr(Vl);
    const unsigned uPh = smaddr(Ph), uPl = smaddr(Pl);

    // ---- load pre-split Q (64x64) and K (256x64) ----
    {
        int idx = tid;                     // 0..255 -> 2 iters cover 512 chunks
#pragma unroll
        for (int i=0;i<2;i++){
            int r = (idx + i*256) >> 3, c8 = ((idx + i*256) & 7) << 3;
            size_t g = ((size_t)(b*TT + qbase + r))*DM + h*HD + c8;
            *(uint4*)&Qh[r*AQP + c8] = *(const uint4*)&g_Qh[g];
            *(uint4*)&Ql[r*AQP + c8] = *(const uint4*)&g_Ql[g];
        }
#pragma unroll
        for (int i=0;i<8;i++){
            int r = (idx + i*256) >> 3, c8 = ((idx + i*256) & 7) << 3;
            size_t g = ((size_t)(b*TT + kstart + r))*DM + h*HD + c8;
            *(uint4*)&Kh[r*AKP + c8] = *(const uint4*)&g_Kh[g];
            *(uint4*)&Kl[r*AKP + c8] = *(const uint4*)&g_Kl[g];
        }
    }
    __syncthreads();

    // ---- S = Q K^T ----
    const int rloc0 = wm*16 + lq;
    const int rloc1 = rloc0 + 8;
    float sc[16][4];
#pragma unroll
    for (int nt=0; nt<16; nt++)
#pragma unroll
        for (int cc=0; cc<4; cc++) sc[nt][cc] = 0.f;

#pragma unroll
    for (int ks=0; ks<64; ks+=16){
        unsigned ahi[4], alo[4];
        unsigned aoff = (unsigned)(((wm*16 + am_r)*AQP + ks + am_c)*2);
        ldsm_x4(ahi[0],ahi[1],ahi[2],ahi[3], uQh + aoff);
        ldsm_x4(alo[0],alo[1],alo[2],alo[3], uQl + aoff);
#pragma unroll
        for (int np=0; np<8; np++){
            unsigned bh0,bh1,bh2,bh3, bl0,bl1,bl2,bl3;
            unsigned boff = (unsigned)(((wn*128 + np*16 + n_r)*AKP + ks + n_k)*2);
            ldsm_x4(bh0,bh1,bh2,bh3, uKh + boff);
            ldsm_x4(bl0,bl1,bl2,bl3, uKl + boff);
            mma16816(sc[2*np],   ahi, bh0, bh1);
            mma16816(sc[2*np],   ahi, bl0, bl1);
            mma16816(sc[2*np],   alo, bh0, bh1);
            mma16816(sc[2*np+1], ahi, bh2, bh3);
            mma16816(sc[2*np+1], ahi, bl2, bl3);
            mma16816(sc[2*np+1], alo, bh2, bh3);
        }
    }

    // ---- alibi + causal mask, cross-warp softmax ----
    const float slope = exp2f(-0.5f*(float)(h+1));
    const int i0 = qbase + rloc0;
    const int i1 = i0 + 8;
    float m0 = -1e30f, m1 = -1e30f;
#pragma unroll
    for (int nt=0; nt<16; nt++){
        int j = kstart + wn*128 + nt*8 + (la3<<1);
        float s;
        s = sc[nt][0]*0.125f + slope*(float)(i0 - j);
        if (j   > i0) s = -1e30f; sc[nt][0]=s; m0=fmaxf(m0,s);
        s = sc[nt][1]*0.125f + slope*(float)(i0 - j - 1);
        if (j+1 > i0) s = -1e30f; sc[nt][1]=s; m0=fmaxf(m0,s);
        s = sc[nt][2]*0.125f + slope*(float)(i1 - j);
        if (j   > i1) s = -1e30f; sc[nt][2]=s; m1=fmaxf(m1,s);
        s = sc[nt][3]*0.125f + slope*(float)(i1 - j - 1);
        if (j+1 > i1) s = -1e30f; sc[nt][3]=s; m1=fmaxf(m1,s);
    }
    m0 = fmaxf(m0, __shfl_xor_sync(0xffffffffu, m0, 1));
    m0 = fmaxf(m0, __shfl_xor_sync(0xffffffffu, m0, 2));
    m1 = fmaxf(m1, __shfl_xor_sync(0xffffffffu, m1, 1));
    m1 = fmaxf(m1, __shfl_xor_sync(0xffffffffu, m1, 2));
    if (la3 == 0){
        Rm[rloc0*2 + wn] = m0;
        Rm[rloc1*2 + wn] = m1;
    }
    __syncthreads();
    m0 = fmaxf(Rm[rloc0*2], Rm[rloc0*2 + 1]);
    m1 = fmaxf(Rm[rloc1*2], Rm[rloc1*2 + 1]);

    float l0 = 0.f, l1 = 0.f;
#pragma unroll
    for (int nt=0; nt<16; nt++){
        float p;
        p = __expf(sc[nt][0]-m0); sc[nt][0]=p; l0+=p;
        p = __expf(sc[nt][1]-m0); sc[nt][1]=p; l0+=p;
        p = __expf(sc[nt][2]-m1); sc[nt][2]=p; l1+=p;
        p = __expf(sc[nt][3]-m1); sc[nt][3]=p; l1+=p;
    }
    l0 += __shfl_xor_sync(0xffffffffu, l0, 1);
    l0 += __shfl_xor_sync(0xffffffffu, l0, 2);
    l1 += __shfl_xor_sync(0xffffffffu, l1, 1);
    l1 += __shfl_xor_sync(0xffffffffu, l1, 2);
    if (la3 == 0){
        Rs[rloc0*2 + wn] = l0;
        Rs[rloc1*2 + wn] = l1;
    }
    __syncthreads();   // all Q reads done; P may overwrite Q region after this
    const float inv0 = 1.f / (Rs[rloc0*2] + Rs[rloc0*2 + 1]);
    const float inv1 = 1.f / (Rs[rloc1*2] + Rs[rloc1*2 + 1]);

#pragma unroll
    for (int nt=0; nt<16; nt++){
        int c = wn*128 + nt*8 + (la3<<1);
        unsigned ph, pl;
        split_bf2(sc[nt][0]*inv0, sc[nt][1]*inv0, ph, pl);
        *(unsigned*)&Ph[rloc0*APP + c] = ph;
        *(unsigned*)&Pl[rloc0*APP + c] = pl;
        split_bf2(sc[nt][2]*inv1, sc[nt][3]*inv1, ph, pl);
        *(unsigned*)&Ph[rloc1*APP + c] = ph;
        *(unsigned*)&Pl[rloc1*APP + c] = pl;
    }
    __syncthreads();

    // ---- write full attn rows (band = hi+lo, rest = 0); load V (pre-split, over K) ----
    if (has_attn){
        const float4 zero4 = make_float4(0.f,0.f,0.f,0.f);
#pragma unroll 4
        for (int i=0;i<128;i++){
            int idx = tid + i*256;
            int r = idx >> 9;
            int c4 = (idx & 511) << 2;
            int cc = c4 - kstart;
            float4 v = zero4;
            if (cc >= 0 && cc < 256){
                __nv_bfloat162 h0 = *(__nv_bfloat162*)&Ph[r*APP + cc];
                __nv_bfloat162 h1 = *(__nv_bfloat162*)&Ph[r*APP + cc + 2];
                __nv_bfloat162 q0 = *(__nv_bfloat162*)&Pl[r*APP + cc];
                __nv_bfloat162 q1 = *(__nv_bfloat162*)&Pl[r*APP + cc + 2];
                float2 a0 = __bfloat1622float2(h0), a1 = __bfloat1622float2(h1);
                float2 b0 = __bfloat1622float2(q0), b1 = __bfloat1622float2(q1);
                v = make_float4(a0.x+b0.x, a0.y+b0.y, a1.x+b1.x, a1.y+b1.y);
            }
            *(float4*)&attn_out[((size_t)bh*TT + qbase + r)*TT + c4] = v;
        }
    }
#pragma unroll
    for (int i=0;i<8;i++){
        int idx = tid + i*256;
        int r = idx >> 3, c8 = (idx & 7) << 3;
        size_t g = ((size_t)(b*TT + kstart + r))*DM + h*HD + c8;
        *(uint4*)&Vh[r*AKP + c8] = *(const uint4*)&g_Vh[g];
        *(uint4*)&Vl[r*AKP + c8] = *(const uint4*)&g_Vl[g];
    }
    __syncthreads();

    // ---- O = P @ V : warp tile 16 rows x 32 cols ----
    float oc[4][4];
#pragma unroll
    for (int nt=0; nt<4; nt++)
#pragma unroll
        for (int cc=0; cc<4; cc++) oc[nt][cc] = 0.f;

#pragma unroll 4
    for (int ks=0; ks<256; ks+=16){
        unsigned ahi[4], alo[4];
        unsigned aoff = (unsigned)(((wm*16 + am_r)*APP + ks + am_c)*2);
        ldsm_x4(ahi[0],ahi[1],ahi[2],ahi[3], uPh + aoff);
        ldsm_x4(alo[0],alo[1],alo[2],alo[3], uPl + aoff);
#pragma unroll
        for (int np=0; np<2; np++){
            unsigned bh0,bh1,bh2,bh3, bl0,bl1,bl2,bl3;
            unsigned boff = (unsigned)(((ks + t_k)*AKP + wn*32 + np*16 + t_n)*2);
            ldsm_x4t(bh0,bh1,bh2,bh3, uVh + boff);
            ldsm_x4t(bl0,bl1,bl2,bl3, uVl + boff);
            mma16816(oc[2*np],   ahi, bh0, bh1);
            mma16816(oc[2*np],   ahi, bl0, bl1);
            mma16816(oc[2*np],   alo, bh0, bh1);
            mma16816(oc[2*np+1], ahi, bh2, bh3);
            mma16816(oc[2*np+1], ahi, bl2, bl3);
            mma16816(oc[2*np+1], alo, bh2, bh3);
        }
    }

    // ---- write O pre-split (bf16 hi/lo) in (b*T+t, h*64+d) layout ----
#pragma unroll
    for (int nt=0; nt<4; nt++){
        int col = h*HD + wn*32 + nt*8 + (la3<<1);
        size_t rg = (size_t)(b*TT + qbase + rloc0);
        unsigned h0,l0;
        split_bf2(oc[nt][0], oc[nt][1], h0, l0);
        *(unsigned*)&g_Oh[rg*DM + col] = h0;
        *(unsigned*)&g_Ol[rg*DM + col] = l0;
        split_bf2(oc[nt][2], oc[nt][3], h0, l0);
        *(unsigned*)&g_Oh[(rg+8)*DM + col] = h0;
        *(unsigned*)&g_Ol[(rg+8)*DM + col] = l0;
    }
}

// ======================= host launcher =======================
extern "C" void kernel_launch(void* const* d_in, const int* in_sizes, int n_in,
                              void* d_out, int out_size)
{
    const float* x  = (const float*)d_in[0];
    const float* Wq = (const float*)d_in[1];
    const float* bq = (const float*)d_in[2];
    const float* Wk = (const float*)d_in[3];
    const float* bk = (const float*)d_in[4];
    const float* Wv = (const float*)d_in[5];
    const float* bv = (const float*)d_in[6];
    const float* Wo = (const float*)d_in[7];
    const float* bo = (const float*)d_in[8];
    float* out = (float*)d_out;

    const long long OUT_ELEMS  = (long long)MROWS*DM;
    const long long ATTN_ELEMS = (long long)BB*NH*TT*TT;
    const int has_attn = ((long long)out_size >= OUT_ELEMS + ATTN_ELEMS) ? 1 : 0;
    float* attn = has_attn ? (out + OUT_ELEMS) : nullptr;

    // device-global symbol addresses
    __nv_bfloat16 *pxh,*pxl,*pWqh,*pWql,*pWkh,*pWkl,*pWvh,*pWvl,*pWoh,*pWol;
    __nv_bfloat16 *pQh,*pQl,*pKh,*pKl,*pVh,*pVl,*pOh,*pOl;
    cudaGetSymbolAddress((void**)&pxh, g_xh);   cudaGetSymbolAddress((void**)&pxl, g_xl);
    cudaGetSymbolAddress((void**)&pWqh, g_Wqh); cudaGetSymbolAddress((void**)&pWql, g_Wql);
    cudaGetSymbolAddress((void**)&pWkh, g_Wkh); cudaGetSymbolAddress((void**)&pWkl, g_Wkl);
    cudaGetSymbolAddress((void**)&pWvh, g_Wvh); cudaGetSymbolAddress((void**)&pWvl, g_Wvl);
    cudaGetSymbolAddress((void**)&pWoh, g_Woh); cudaGetSymbolAddress((void**)&pWol, g_Wol);
    cudaGetSymbolAddress((void**)&pQh, g_Qh);   cudaGetSymbolAddress((void**)&pQl, g_Ql);
    cudaGetSymbolAddress((void**)&pKh, g_Kh);   cudaGetSymbolAddress((void**)&pKl, g_Kl);
    cudaGetSymbolAddress((void**)&pVh, g_Vh);   cudaGetSymbolAddress((void**)&pVl, g_Vl);
    cudaGetSymbolAddress((void**)&pOh, g_Oh);   cudaGetSymbolAddress((void**)&pOl, g_Ol);

    static int attr_done = 0;
    if (!attr_done){
        cudaFuncSetAttribute(gemm_bf3_kernel, cudaFuncAttributeMaxDynamicSharedMemorySize, G_SMEM_BYTES);
        cudaFuncSetAttribute(attn_kernel, cudaFuncAttributeMaxDynamicSharedMemorySize, A_SMEM_BYTES);
        attr_done = 1;
    }

    // 1) pre-split x and weights to bf16 hi/lo
    presplit_kernel<<<512, 256>>>(x,  pxh,  pxl,  MROWS*DM/4);
    presplit_kernel<<<256, 256>>>(Wq, pWqh, pWql, DM*DM/4);
    presplit_kernel<<<256, 256>>>(Wk, pWkh, pWkl, DM*DM/4);
    presplit_kernel<<<256, 256>>>(Wv, pWvh, pWvl, DM*DM/4);
    presplit_kernel<<<256, 256>>>(Wo, pWoh, pWol, DM*DM/4);

    // 2) fused Q/K/V projections (write pre-split bf16 outputs)
    gemm_bf3_kernel<<<dim3(DM/128, MROWS/128, 3), 256, G_SMEM_BYTES>>>(
        pxh, pxl,
        pWqh, pWql, pWkh, pWkl, pWvh, pWvl,
        bq, bk, bv,
        pQh, pQl, pKh, pKl, pVh, pVl,
        nullptr, 1);

    // 3) banded attention (writes full attn rows; O as bf16 hi/lo)
    attn_kernel<<<dim3(TT/64, BB*NH), 256, A_SMEM_BYTES>>>(attn, has_attn);

    // 4) output projection (fp32 out)
    gemm_bf3_kernel<<<dim3(DM/128, MROWS/128, 1), 256, G_SMEM_BYTES>>>(
        pOh, pOl,
        pWoh, pWol, pWoh, pWol, pWoh, pWol,
        bo, bo, bo,
        nullptr, nullptr, nullptr, nullptr, nullptr, nullptr,
        out, 0);
}

// round 7
// speedup vs baseline: 1.3255x; 1.3255x over previous
#include <cuda_runtime.h>
#include <cuda_bf16.h>
#include <cuda_fp16.h>
#include <math.h>

// Problem constants
#define BB 2
#define TT 2048
#define DM 1024
#define NH 16
#define HD 64
#define MROWS (BB*TT)     // 4096

// ---------------- scratch (device globals; no allocation allowed) ----------------
__device__ float g_Q[MROWS*DM];
__device__ float g_K[MROWS*DM];
__device__ float g_V[MROWS*DM];
__device__ float g_O[MROWS*DM];

// ---------------- bf16 split helpers (attention path) ----------------
__device__ __forceinline__ void split_bf2(float x, float y, unsigned &h, unsigned &l){
    __nv_bfloat162 hh = __floats2bfloat162_rn(x, y);
    float2 hf = __bfloat1622float2(hh);
    __nv_bfloat162 ll = __floats2bfloat162_rn(x - hf.x, y - hf.y);
    h = *(unsigned*)&hh;
    l = *(unsigned*)&ll;
}
// ---------------- fp16 helpers (projection path) ----------------
__device__ __forceinline__ void split_h2(float x, float y, unsigned &h, unsigned &l){
    __half2 hh = __floats2half2_rn(x, y);
    float2 hf = __half22float2(hh);
    __half2 ll = __floats2half2_rn(x - hf.x, y - hf.y);
    h = *(unsigned*)&hh;
    l = *(unsigned*)&ll;
}
__device__ __forceinline__ unsigned cvt_h2(float x, float y){
    __half2 hh = __floats2half2_rn(x, y);
    return *(unsigned*)&hh;
}

__device__ __forceinline__ unsigned smaddr(const void* p){
    return (unsigned)__cvta_generic_to_shared(p);
}
__device__ __forceinline__ void ldsm_x4(unsigned &r0, unsigned &r1, unsigned &r2, unsigned &r3, unsigned a){
    asm volatile("ldmatrix.sync.aligned.m8n8.x4.shared.b16 {%0,%1,%2,%3}, [%4];"
        : "=r"(r0),"=r"(r1),"=r"(r2),"=r"(r3) : "r"(a));
}
__device__ __forceinline__ void ldsm_x4t(unsigned &r0, unsigned &r1, unsigned &r2, unsigned &r3, unsigned a){
    asm volatile("ldmatrix.sync.aligned.m8n8.x4.trans.shared.b16 {%0,%1,%2,%3}, [%4];"
        : "=r"(r0),"=r"(r1),"=r"(r2),"=r"(r3) : "r"(a));
}
// bf16 mma (attention)
__device__ __forceinline__ void mma16816(float c[4], const unsigned a[4], unsigned b0, unsigned b1){
    asm volatile(
      "mma.sync.aligned.m16n8k16.row.col.f32.bf16.bf16.f32 "
      "{%0,%1,%2,%3}, {%4,%5,%6,%7}, {%8,%9}, {%0,%1,%2,%3};"
      : "+f"(c[0]), "+f"(c[1]), "+f"(c[2]), "+f"(c[3])
      : "r"(a[0]), "r"(a[1]), "r"(a[2]), "r"(a[3]), "r"(b0), "r"(b1));
}
// fp16 mma (projections)
__device__ __forceinline__ void mma16816f(float c[4], const unsigned a[4], unsigned b0, unsigned b1){
    asm volatile(
      "mma.sync.aligned.m16n8k16.row.col.f32.f16.f16.f32 "
      "{%0,%1,%2,%3}, {%4,%5,%6,%7}, {%8,%9}, {%0,%1,%2,%3};"
      : "+f"(c[0]), "+f"(c[1]), "+f"(c[2]), "+f"(c[3])
      : "r"(a[0]), "r"(a[1]), "r"(a[2]), "r"(a[3]), "r"(b0), "r"(b1));
}

// ======================= GEMM: C[M,N] = A[M,K] @ W[K,N] + bias (fp16 2-term) =======================
// 128x128 tile, BK=32, 256 threads (8 warps, warp tile 32x64). A split to fp16 hi/lo in smem,
// B rounded to single fp16. C = (Ah+Al) @ Bh : 2 MMAs per tile-step. z selects (W,bias,C).
#define GAP 40    // A smem pitch (fp16 elems): 80B rows -> ldmatrix conflict-free
#define GBP 136   // B smem pitch (fp16 elems): 272B rows -> conflict-free

__global__ void __launch_bounds__(256,2) gemm3_kernel(
    const float* __restrict__ A,
    const float* __restrict__ W0, const float* __restrict__ W1, const float* __restrict__ W2,
    const float* __restrict__ bb0, const float* __restrict__ bb1, const float* __restrict__ bb2,
    float* __restrict__ C0, float* __restrict__ C1, float* __restrict__ C2)
{
    __shared__ __align__(16) unsigned short Ah[128*GAP];
    __shared__ __align__(16) unsigned short Al[128*GAP];
    __shared__ __align__(16) unsigned short Bs[32*GBP];

    const int z = blockIdx.z;
    const float* W    = (z==0) ? W0  : (z==1) ? W1  : W2;
    const float* bias = (z==0) ? bb0 : (z==1) ? bb1 : bb2;
    float*       C    = (z==0) ? C0  : (z==1) ? C1  : C2;

    const int tid  = threadIdx.x;
    const int warp = tid >> 5, lane = tid & 31;
    const int wm = warp >> 1;        // 0..3
    const int wn = warp & 1;         // 0..1
    const int bm = blockIdx.y * 128;
    const int bn = blockIdx.x * 128;

    float acc[2][8][4];
#pragma unroll
    for (int mt=0; mt<2; mt++)
#pragma unroll
      for (int nt=0; nt<8; nt++)
#pragma unroll
        for (int cc=0; cc<4; cc++) acc[mt][nt][cc] = 0.f;

    // loaders
    const int ar = tid >> 3;            // 0..31
    const int ac = (tid & 7) << 2;      // 0..28
    const int br = tid >> 5;            // 0..7
    const int bc = (tid & 31) << 2;     // 0..124

    // ldmatrix per-lane offsets
    const int a_r = lane & 15;
    const int a_c = (lane >> 4) << 3;          // 0 or 8
    const int b_k = (((lane >> 3) & 1) << 3) + (lane & 7);
    const int b_n = ((lane >> 4) & 1) << 3;    // 0 or 8

    const unsigned uAh = smaddr(Ah), uAl = smaddr(Al);
    const unsigned uBs = smaddr(Bs);

    const int la3 = lane & 3, lq = lane >> 2;

    for (int k0 = 0; k0 < DM; k0 += 32){
#pragma unroll
        for (int i=0;i<4;i++){
            float4 va = *(const float4*)&A[(size_t)(bm + ar + i*32)*DM + k0 + ac];
            float4 vb = *(const float4*)&W[(size_t)(k0 + br + i*8)*DM + bn + bc];
            unsigned h0,l0,h1,l1;
            split_h2(va.x, va.y, h0, l0);
            split_h2(va.z, va.w, h1, l1);
            *(uint2*)&Ah[(ar + i*32)*GAP + ac] = make_uint2(h0,h1);
            *(uint2*)&Al[(ar + i*32)*GAP + ac] = make_uint2(l0,l1);
            *(uint2*)&Bs[(br + i*8)*GBP + bc] =
                make_uint2(cvt_h2(vb.x, vb.y), cvt_h2(vb.z, vb.w));
        }
        __syncthreads();

#pragma unroll
        for (int ks = 0; ks < 32; ks += 16){
            unsigned ahi[2][4], alo[2][4];
#pragma unroll
            for (int mt=0; mt<2; mt++){
                unsigned off = (unsigned)(((wm*32 + mt*16 + a_r)*GAP + ks + a_c)*2);
                ldsm_x4(ahi[mt][0],ahi[mt][1],ahi[mt][2],ahi[mt][3], uAh + off);
                ldsm_x4(alo[mt][0],alo[mt][1],alo[mt][2],alo[mt][3], uAl + off);
            }
#pragma unroll
            for (int np=0; np<4; np++){
                unsigned b0,b1,b2,b3;
                unsigned off = (unsigned)(((ks + b_k)*GBP + wn*64 + np*16 + b_n)*2);
                ldsm_x4t(b0,b1,b2,b3, uBs + off);
#pragma unroll
                for (int mt=0; mt<2; mt++){
                    mma16816f(acc[mt][2*np],   ahi[mt], b0, b1);
                    mma16816f(acc[mt][2*np],   alo[mt], b0, b1);
                    mma16816f(acc[mt][2*np+1], ahi[mt], b2, b3);
                    mma16816f(acc[mt][2*np+1], alo[mt], b2, b3);
                }
            }
        }
        __syncthreads();
    }

#pragma unroll
    for (int mt=0; mt<2; mt++){
#pragma unroll
        for (int nt=0; nt<8; nt++){
            int col = bn + wn*64 + nt*8 + (la3<<1);
            float b0 = bias[col], b1 = bias[col+1];
            int r0 = bm + wm*32 + mt*16 + lq;
            *(float2*)&C[(size_t)r0*DM + col]     = make_float2(acc[mt][nt][0] + b0, acc[mt][nt][1] + b1);
            *(float2*)&C[(size_t)(r0+8)*DM + col] = make_float2(acc[mt][nt][2] + b0, acc[mt][nt][3] + b1);
        }
    }
}

// ======================= Fused banded attention (bf16x3) — unchanged from R4 =======================
#define AQP 72    // Q pitch (bf16)
#define AKP 72    // K/V pitch (bf16)
#define APP 264   // P pitch (bf16)

#define O_PH 0
#define O_PL (O_PH + 64*APP*2)            // 33792
#define O_QH 0                            // aliases P (Q dies before P is written)
#define O_QL (O_QH + 64*AQP*2)            // 9216
#define O_KH (O_PL + 64*APP*2)            // 67584
#define O_KL (O_KH + 256*AKP*2)           // 104448
#define O_VH O_KH
#define O_VL O_KL
#define O_RM (O_KL + 256*AKP*2)           // 141312
#define O_RS (O_RM + 512)                 // 141824
#define A_SMEM_BYTES (O_RS + 512)         // 142336

__global__ void __launch_bounds__(256) attn_kernel(float* __restrict__ attn_out, int has_attn)
{
    extern __shared__ char smb[];
    unsigned short* Qh = (unsigned short*)(smb + O_QH);
    unsigned short* Ql = (unsigned short*)(smb + O_QL);
    unsigned short* Kh = (unsigned short*)(smb + O_KH);
    unsigned short* Kl = (unsigned short*)(smb + O_KL);
    unsigned short* Vh = (unsigned short*)(smb + O_VH);
    unsigned short* Vl = (unsigned short*)(smb + O_VL);
    unsigned short* Ph = (unsigned short*)(smb + O_PH);
    unsigned short* Pl = (unsigned short*)(smb + O_PL);
    float* Rm = (float*)(smb + O_RM);
    float* Rs = (float*)(smb + O_RS);

    const int tid = threadIdx.x, warp = tid>>5, lane = tid&31;
    const int wm = warp >> 1;
    const int wn = warp & 1;
    const int la3 = lane & 3;
    const int lq  = lane >> 2;
    const int bh = blockIdx.y;
    const int b = bh >> 4, h = bh & 15;
    const int qbase = blockIdx.x * 64;
    const int qblk  = qbase >> 7;
    const int kstart = (qblk==0) ? 0 : (qblk-1)*128;

    const int am_r = lane & 15;
    const int am_c = (lane >> 4) << 3;
    const int t_k = (((lane >> 3) & 1) << 3) + (lane & 7);
    const int t_n = ((lane >> 4) & 1) << 3;
    const int n_r = ((((lane >> 3) & 2) << 2)) + (lane & 7);
    const int n_k = (((lane >> 3) & 1) << 3);

    const unsigned uQh = smaddr(Qh), uQl = smaddr(Ql);
    const unsigned uKh = smaddr(Kh), uKl = smaddr(Kl);
    const unsigned uVh = smaddr(Vh), uVl = smaddr(Vl);
    const unsigned uPh = smaddr(Ph), uPl = smaddr(Pl);

    // ---- load Q (64x64) and K (256x64), split to bf16 hi/lo ----
#pragma unroll
    for (int i=0;i<4;i++){
        int idx = tid + i*256;
        int r = idx >> 4, c = (idx & 15) << 2;
        float4 v = *(const float4*)&g_Q[((size_t)(b*TT + qbase + r))*DM + h*HD + c];
        unsigned h0,l0,h1,l1;
        split_bf2(v.x,v.y,h0,l0); split_bf2(v.z,v.w,h1,l1);
        *(uint2*)&Qh[r*AQP + c] = make_uint2(h0,h1);
        *(uint2*)&Ql[r*AQP + c] = make_uint2(l0,l1);
    }
#pragma unroll
    for (int i=0;i<16;i++){
        int idx = tid + i*256;
        int r = idx >> 4, c = (idx & 15) << 2;
        float4 v = *(const float4*)&g_K[((size_t)(b*TT + kstart + r))*DM + h*HD + c];
        unsigned h0,l0,h1,l1;
        split_bf2(v.x,v.y,h0,l0); split_bf2(v.z,v.w,h1,l1);
        *(uint2*)&Kh[r*AKP + c] = make_uint2(h0,h1);
        *(uint2*)&Kl[r*AKP + c] = make_uint2(l0,l1);
    }
    __syncthreads();

    // ---- S = Q K^T ----
    const int rloc0 = wm*16 + lq;
    const int rloc1 = rloc0 + 8;
    float sc[16][4];
#pragma unroll
    for (int nt=0; nt<16; nt++)
#pragma unroll
        for (int cc=0; cc<4; cc++) sc[nt][cc] = 0.f;

#pragma unroll
    for (int ks=0; ks<64; ks+=16){
        unsigned ahi[4], alo[4];
        unsigned aoff = (unsigned)(((wm*16 + am_r)*AQP + ks + am_c)*2);
        ldsm_x4(ahi[0],ahi[1],ahi[2],ahi[3], uQh + aoff);
        ldsm_x4(alo[0],alo[1],alo[2],alo[3], uQl + aoff);
#pragma unroll
        for (int np=0; np<8; np++){
            unsigned bh0,bh1,bh2,bh3, bl0,bl1,bl2,bl3;
            unsigned boff = (unsigned)(((wn*128 + np*16 + n_r)*AKP + ks + n_k)*2);
            ldsm_x4(bh0,bh1,bh2,bh3, uKh + boff);
            ldsm_x4(bl0,bl1,bl2,bl3, uKl + boff);
            mma16816(sc[2*np],   ahi, bh0, bh1);
            mma16816(sc[2*np],   ahi, bl0, bl1);
            mma16816(sc[2*np],   alo, bh0, bh1);
            mma16816(sc[2*np+1], ahi, bh2, bh3);
            mma16816(sc[2*np+1], ahi, bl2, bl3);
            mma16816(sc[2*np+1], alo, bh2, bh3);
        }
    }

    // ---- alibi + causal mask, cross-warp softmax ----
    const float slope = exp2f(-0.5f*(float)(h+1));
    const int i0 = qbase + rloc0;
    const int i1 = i0 + 8;
    float m0 = -1e30f, m1 = -1e30f;
#pragma unroll
    for (int nt=0; nt<16; nt++){
        int j = kstart + wn*128 + nt*8 + (la3<<1);
        float s;
        s = sc[nt][0]*0.125f + slope*(float)(i0 - j);
        if (j   > i0) s = -1e30f; sc[nt][0]=s; m0=fmaxf(m0,s);
        s = sc[nt][1]*0.125f + slope*(float)(i0 - j - 1);
        if (j+1 > i0) s = -1e30f; sc[nt][1]=s; m0=fmaxf(m0,s);
        s = sc[nt][2]*0.125f + slope*(float)(i1 - j);
        if (j   > i1) s = -1e30f; sc[nt][2]=s; m1=fmaxf(m1,s);
        s = sc[nt][3]*0.125f + slope*(float)(i1 - j - 1);
        if (j+1 > i1) s = -1e30f; sc[nt][3]=s; m1=fmaxf(m1,s);
    }
    m0 = fmaxf(m0, __shfl_xor_sync(0xffffffffu, m0, 1));
    m0 = fmaxf(m0, __shfl_xor_sync(0xffffffffu, m0, 2));
    m1 = fmaxf(m1, __shfl_xor_sync(0xffffffffu, m1, 1));
    m1 = fmaxf(m1, __shfl_xor_sync(0xffffffffu, m1, 2));
    if (la3 == 0){
        Rm[rloc0*2 + wn] = m0;
        Rm[rloc1*2 + wn] = m1;
    }
    __syncthreads();
    m0 = fmaxf(Rm[rloc0*2], Rm[rloc0*2 + 1]);
    m1 = fmaxf(Rm[rloc1*2], Rm[rloc1*2 + 1]);

    float l0 = 0.f, l1 = 0.f;
#pragma unroll
    for (int nt=0; nt<16; nt++){
        float p;
        p = __expf(sc[nt][0]-m0); sc[nt][0]=p; l0+=p;
        p = __expf(sc[nt][1]-m0); sc[nt][1]=p; l0+=p;
        p = __expf(sc[nt][2]-m1); sc[nt][2]=p; l1+=p;
        p = __expf(sc[nt][3]-m1); sc[nt][3]=p; l1+=p;
    }
    l0 += __shfl_xor_sync(0xffffffffu, l0, 1);
    l0 += __shfl_xor_sync(0xffffffffu, l0, 2);
    l1 += __shfl_xor_sync(0xffffffffu, l1, 1);
    l1 += __shfl_xor_sync(0xffffffffu, l1, 2);
    if (la3 == 0){
        Rs[rloc0*2 + wn] = l0;
        Rs[rloc1*2 + wn] = l1;
    }
    __syncthreads();   // all Q reads done; P may overwrite Q region after this
    const float inv0 = 1.f / (Rs[rloc0*2] + Rs[rloc0*2 + 1]);
    const float inv1 = 1.f / (Rs[rloc1*2] + Rs[rloc1*2 + 1]);

#pragma unroll
    for (int nt=0; nt<16; nt++){
        int c = wn*128 + nt*8 + (la3<<1);
        unsigned ph, pl;
        split_bf2(sc[nt][0]*inv0, sc[nt][1]*inv0, ph, pl);
        *(unsigned*)&Ph[rloc0*APP + c] = ph;
        *(unsigned*)&Pl[rloc0*APP + c] = pl;
        split_bf2(sc[nt][2]*inv1, sc[nt][3]*inv1, ph, pl);
        *(unsigned*)&Ph[rloc1*APP + c] = ph;
        *(unsigned*)&Pl[rloc1*APP + c] = pl;
    }
    __syncthreads();

    // ---- write full attn rows (band = hi+lo, rest = 0); load V (pre-split, over K) ----
    if (has_attn){
        const float4 zero4 = make_float4(0.f,0.f,0.f,0.f);
#pragma unroll 4
        for (int i=0;i<128;i++){
            int idx = tid + i*256;
            int r = idx >> 9;
            int c4 = (idx & 511) << 2;
            int cc = c4 - kstart;
            float4 v = zero4;
            if (cc >= 0 && cc < 256){
                __nv_bfloat162 h0 = *(__nv_bfloat162*)&Ph[r*APP + cc];
                __nv_bfloat162 h1 = *(__nv_bfloat162*)&Ph[r*APP + cc + 2];
                __nv_bfloat162 q0 = *(__nv_bfloat162*)&Pl[r*APP + cc];
                __nv_bfloat162 q1 = *(__nv_bfloat162*)&Pl[r*APP + cc + 2];
                float2 a0 = __bfloat1622float2(h0), a1 = __bfloat1622float2(h1);
                float2 b0 = __bfloat1622float2(q0), b1 = __bfloat1622float2(q1);
                v = make_float4(a0.x+b0.x, a0.y+b0.y, a1.x+b1.x, a1.y+b1.y);
            }
            *(float4*)&attn_out[((size_t)bh*TT + qbase + r)*TT + c4] = v;
        }
    }
#pragma unroll
    for (int i=0;i<16;i++){
        int idx = tid + i*256;
        int r = idx >> 4, c = (idx & 15) << 2;
        float4 v = *(const float4*)&g_V[((size_t)(b*TT + kstart + r))*DM + h*HD + c];
        unsigned h0,l0,h1,l1;
        split_bf2(v.x,v.y,h0,l0); split_bf2(v.z,v.w,h1,l1);
        *(uint2*)&Vh[r*AKP + c] = make_uint2(h0,h1);
        *(uint2*)&Vl[r*AKP + c] = make_uint2(l0,l1);
    }
    __syncthreads();

    // ---- O = P @ V : warp tile 16 rows x 32 cols ----
    float oc[4][4];
#pragma unroll
    for (int nt=0; nt<4; nt++)
#pragma unroll
        for (int cc=0; cc<4; cc++) oc[nt][cc] = 0.f;

#pragma unroll 4
    for (int ks=0; ks<256; ks+=16){
        unsigned ahi[4], alo[4];
        unsigned aoff = (unsigned)(((wm*16 + am_r)*APP + ks + am_c)*2);
        ldsm_x4(ahi[0],ahi[1],ahi[2],ahi[3], uPh + aoff);
        ldsm_x4(alo[0],alo[1],alo[2],alo[3], uPl + aoff);
#pragma unroll
        for (int np=0; np<2; np++){
            unsigned bh0,bh1,bh2,bh3, bl0,bl1,bl2,bl3;
            unsigned boff = (unsigned)(((ks + t_k)*AKP + wn*32 + np*16 + t_n)*2);
            ldsm_x4t(bh0,bh1,bh2,bh3, uVh + boff);
            ldsm_x4t(bl0,bl1,bl2,bl3, uVl + boff);
            mma16816(oc[2*np],   ahi, bh0, bh1);
            mma16816(oc[2*np],   ahi, bl0, bl1);
            mma16816(oc[2*np],   alo, bh0, bh1);
            mma16816(oc[2*np+1], ahi, bh2, bh3);
            mma16816(oc[2*np+1], ahi, bl2, bl3);
            mma16816(oc[2*np+1], alo, bh2, bh3);
        }
    }

    // ---- write O (fp32) in (b*T+t, h*64+d) layout ----
#pragma unroll
    for (int nt=0; nt<4; nt++){
        int col = h*HD + wn*32 + nt*8 + (la3<<1);
        size_t rg = (size_t)(b*TT + qbase + rloc0);
        *(float2*)&g_O[ rg     *DM + col] = make_float2(oc[nt][0], oc[nt][1]);
        *(float2*)&g_O[(rg + 8)*DM + col] = make_float2(oc[nt][2], oc[nt][3]);
    }
}

// ======================= host launcher =======================
extern "C" void kernel_launch(void* const* d_in, const int* in_sizes, int n_in,
                              void* d_out, int out_size)
{
    const float* x  = (const float*)d_in[0];
    const float* Wq = (const float*)d_in[1];
    const float* bq = (const float*)d_in[2];
    const float* Wk = (const float*)d_in[3];
    const float* bk = (const float*)d_in[4];
    const float* Wv = (const float*)d_in[5];
    const float* bv = (const float*)d_in[6];
    const float* Wo = (const float*)d_in[7];
    const float* bo = (const float*)d_in[8];
    float* out = (float*)d_out;

    const long long OUT_ELEMS  = (long long)MROWS*DM;        // 4,194,304
    const long long ATTN_ELEMS = (long long)BB*NH*TT*TT;     // 134,217,728
    const int has_attn = ((long long)out_size >= OUT_ELEMS + ATTN_ELEMS) ? 1 : 0;
    float* attn = has_attn ? (out + OUT_ELEMS) : nullptr;

    float *pQ, *pK, *pV, *pO;
    cudaGetSymbolAddress((void**)&pQ, g_Q);
    cudaGetSymbolAddress((void**)&pK, g_K);
    cudaGetSymbolAddress((void**)&pV, g_V);
    cudaGetSymbolAddress((void**)&pO, g_O);

    static int attr_done = 0;
    if (!attr_done){
        cudaFuncSetAttribute(attn_kernel, cudaFuncAttributeMaxDynamicSharedMemorySize, A_SMEM_BYTES);
        attr_done = 1;
    }

    // fused Q/K/V projections (fp16 2-term)
    gemm3_kernel<<<dim3(DM/128, MROWS/128, 3), 256>>>(
        x, Wq, Wk, Wv, bq, bk, bv, pQ, pK, pV);

    // banded attention (bf16x3; writes full attn rows: band + zeros)
    attn_kernel<<<dim3(TT/64, BB*NH), 256, A_SMEM_BYTES>>>(attn, has_attn);

    // output projection (fp16 2-term)
    gemm3_kernel<<<dim3(DM/128, MROWS/128, 1), 256>>>(
        pO, Wo, Wo, Wo, bo, bo, bo, out, out, out);
}